// round 1
// baseline (speedup 1.0000x reference)
#include <cuda_runtime.h>
#include <stdint.h>

#define BB 32
#define NGT 20
#define FH 64
#define FW 100
#define AA 9
#define HW (FH*FW)      // 6400
#define TT (HW*AA)      // 57600
#define FG_K 128
#define RPN_BATCH_K 256

// anchors from generate_anchors(): (ratio, scale) = (0.5,{8,16,32}),(1,{...}),(2,{...})
__device__ __constant__ float c_anchors[AA*4] = {
  -84.f,  -40.f,  99.f,  55.f,
 -176.f,  -88.f, 191.f, 103.f,
 -360.f, -184.f, 375.f, 199.f,
  -56.f,  -56.f,  71.f,  71.f,
 -120.f, -120.f, 135.f, 135.f,
 -248.f, -248.f, 263.f, 263.f,
  -36.f,  -80.f,  51.f,  95.f,
  -80.f, -168.f,  95.f, 183.f,
 -168.f, -344.f, 183.f, 359.f
};

// ---------------- Threefry-2x32 (20 rounds), matches JAX ----------------
__host__ __device__ __forceinline__ void tf2x32(uint32_t k0, uint32_t k1,
                                                uint32_t x0, uint32_t x1,
                                                uint32_t& o0, uint32_t& o1) {
  uint32_t ks2 = k0 ^ k1 ^ 0x1BD11BDAu;
  x0 += k0; x1 += k1;
#define TF_RND(r) { x0 += x1; x1 = (x1 << (r)) | (x1 >> (32 - (r))); x1 ^= x0; }
  TF_RND(13) TF_RND(15) TF_RND(26) TF_RND(6)   x0 += k1;  x1 += ks2 + 1u;
  TF_RND(17) TF_RND(29) TF_RND(16) TF_RND(24)  x0 += ks2; x1 += k0  + 2u;
  TF_RND(13) TF_RND(15) TF_RND(26) TF_RND(6)   x0 += k0;  x1 += k1  + 3u;
  TF_RND(17) TF_RND(29) TF_RND(16) TF_RND(24)  x0 += k1;  x1 += ks2 + 4u;
  TF_RND(13) TF_RND(15) TF_RND(26) TF_RND(6)   x0 += ks2; x1 += k0  + 5u;
#undef TF_RND
  o0 = x0; o1 = x1;
}

// ordered float<->int mapping for atomicMax on floats
__device__ __forceinline__ int ford(float f) {
  int i = __float_as_int(f);
  return (i >= 0) ? i : (int)(i ^ 0x7fffffff);
}
__device__ __forceinline__ float funord(int i) {
  return __int_as_float((i >= 0) ? i : (int)(i ^ 0x7fffffff));
}

// ---------------- scratch (device globals; no allocations) ----------------
__device__ int            g_gtmax[BB*NGT];
__device__ unsigned char  g_label[BB*TT];    // 0=bg,1=fg,2=dontcare
__device__ signed char    g_labelf[BB*TT];   // final label -1/0/1
__device__ float4         g_targets[BB*TT];
__device__ unsigned int   g_mfg[BB*TT];
__device__ unsigned int   g_mbg[BB*TT];
__device__ float          g_uw[BB];

struct Anch { float x1,y1,x2,y2,area; bool inside; };

__device__ __forceinline__ Anch anchor_of(int t, float img_w, float img_h,
                                          const float* s_anch) {
  int hw = t / AA;
  int a  = t - hw * AA;
  int h  = hw / FW;
  int w  = hw - h * FW;
  float sx = (float)(w * 16);
  float sy = (float)(h * 16);
  Anch r;
  r.x1 = s_anch[a*4+0] + sx;
  r.y1 = s_anch[a*4+1] + sy;
  r.x2 = s_anch[a*4+2] + sx;
  r.y2 = s_anch[a*4+3] + sy;
  float aw = __fadd_rn(__fsub_rn(r.x2, r.x1), 1.0f);
  float ah = __fadd_rn(__fsub_rn(r.y2, r.y1), 1.0f);
  r.area = __fmul_rn(aw, ah);
  r.inside = (r.x1 >= 0.0f) && (r.y1 >= 0.0f) && (r.x2 < img_w) && (r.y2 < img_h);
  return r;
}

// ov_in value, bit-faithful to the JAX elementwise sequence
__device__ __forceinline__ float ov_val(const Anch& A_, const float* g5) {
  float gx1 = g5[0], gy1 = g5[1], gx2 = g5[2], gy2 = g5[3];
  float gw = __fadd_rn(__fsub_rn(gx2, gx1), 1.0f);
  float gh = __fadd_rn(__fsub_rn(gy2, gy1), 1.0f);
  float ga = __fmul_rn(gw, gh);
  float iw = __fadd_rn(__fsub_rn(fminf(A_.x2, gx2), fmaxf(A_.x1, gx1)), 1.0f);
  float ih = __fadd_rn(__fsub_rn(fminf(A_.y2, gy2), fmaxf(A_.y1, gy1)), 1.0f);
  float inter = __fmul_rn(fmaxf(iw, 0.0f), fmaxf(ih, 0.0f));
  float ua = __fsub_rn(__fadd_rn(A_.area, ga), inter);
  float ov = __fdiv_rn(inter, ua);
  if (gw == 1.0f && gh == 1.0f) ov = 0.0f;   // gt_zero
  if (!A_.inside) ov = -2.0f;                // outside
  return ov;
}

// ---------------- K0: init per-launch scratch ----------------
__global__ void k0_init() {
  int i = threadIdx.x;
  if (i < BB*NGT) g_gtmax[i] = ford(-2.0f);
}

// ---------------- K1: per-(b,g) column max of ov_in ----------------
__global__ void k1_gtmax(const float* __restrict__ gt, const float* __restrict__ iminfo) {
  __shared__ float s_gt[NGT*5];
  __shared__ float s_anch[AA*4];
  __shared__ int   s_max[NGT];
  int b = blockIdx.y;
  int t = blockIdx.x * 256 + threadIdx.x;
  if (threadIdx.x < NGT*5) s_gt[threadIdx.x] = gt[b*NGT*5 + threadIdx.x];
  if (threadIdx.x < AA*4)  s_anch[threadIdx.x] = c_anchors[threadIdx.x];
  if (threadIdx.x < NGT)   s_max[threadIdx.x] = ford(-2.0f);
  __syncthreads();
  float img_h = iminfo[0], img_w = iminfo[1];
  Anch A_ = anchor_of(t, img_w, img_h, s_anch);
  for (int g = 0; g < NGT; g++) {
    float v = ov_val(A_, &s_gt[g*5]);
    int r = __reduce_max_sync(0xffffffffu, ford(v));
    if ((threadIdx.x & 31) == 0) atomicMax(&s_max[g], r);
  }
  __syncthreads();
  if (threadIdx.x < NGT)
    atomicMax(&g_gtmax[b*NGT + threadIdx.x], s_max[threadIdx.x]);
}

// ---------------- K2: labels(pre), targets, threefry draws ----------------
__global__ void k2_main(const float* __restrict__ gt, const float* __restrict__ iminfo,
                        uint32_t kf0, uint32_t kf1, uint32_t kb0, uint32_t kb1) {
  __shared__ float s_gt[NGT*5];
  __shared__ float s_gm[NGT];
  __shared__ float s_anch[AA*4];
  int b = blockIdx.y;
  int t = blockIdx.x * 256 + threadIdx.x;
  if (threadIdx.x < NGT*5) s_gt[threadIdx.x] = gt[b*NGT*5 + threadIdx.x];
  if (threadIdx.x < AA*4)  s_anch[threadIdx.x] = c_anchors[threadIdx.x];
  if (threadIdx.x < NGT) {
    float v = funord(g_gtmax[b*NGT + threadIdx.x]);
    s_gm[threadIdx.x] = (v == 0.0f) ? 1e-5f : v;   // gt_max==0 -> 1e-5
  }
  __syncthreads();
  float img_h = iminfo[0], img_w = iminfo[1];
  Anch A_ = anchor_of(t, img_w, img_h, s_anch);

  float mx = -3.0f; int amax = 0; bool keep = false;
  for (int g = 0; g < NGT; g++) {
    float v = ov_val(A_, &s_gt[g*5]);
    if (v > mx) { mx = v; amax = g; }      // first-occurrence argmax
    keep = keep || (v == s_gm[g]);
  }

  unsigned char L = 2;
  if (A_.inside) {
    if (keep || mx >= 0.7f) L = 1;
    else if (mx < 0.3f)     L = 0;
  }
  size_t gi = (size_t)b * TT + t;
  g_label[gi]  = L;
  g_labelf[gi] = (L == 2) ? (signed char)-1 : (signed char)L;

  float4 tg = make_float4(0.f, 0.f, 0.f, 0.f);
  if (A_.inside) {
    const float* g5 = &s_gt[amax*5];
    float ew = A_.x2 - A_.x1 + 1.0f, eh = A_.y2 - A_.y1 + 1.0f;
    float ecx = A_.x1 + 0.5f*ew,     ecy = A_.y1 + 0.5f*eh;
    float gw = g5[2] - g5[0] + 1.0f, gh = g5[3] - g5[1] + 1.0f;
    float gcx = g5[0] + 0.5f*gw,     gcy = g5[1] + 0.5f*gh;
    tg.x = (gcx - ecx) / ew;
    tg.y = (gcy - ecy) / eh;
    tg.z = logf(gw / ew);
    tg.w = logf(gh / eh);
  }
  g_targets[gi] = tg;

  // partitionable threefry: bits = o0 ^ o1 of cipher(key, (hi=0, lo=i)); m = bits>>9
  uint32_t i = (uint32_t)gi, o0, o1;
  tf2x32(kf0, kf1, 0u, i, o0, o1); g_mfg[gi] = (o0 ^ o1) >> 9;
  tf2x32(kb0, kb1, 0u, i, o0, o1); g_mbg[gi] = (o0 ^ o1) >> 9;
}

// ---------------- K3: per-batch k-smallest selection ----------------
__device__ void kth_from_hist(const unsigned int* hist, int nbins, int k,
                              int* s_scan, int* bc) {
  int tid = threadIdx.x;
  int bpt = nbins >> 10;           // bins per thread (4 or 2)
  int base = tid * bpt;
  int local = 0;
  for (int i = 0; i < bpt; i++) local += (int)hist[base + i];
  s_scan[tid] = local; __syncthreads();
  for (int off = 1; off < 1024; off <<= 1) {
    int v = (tid >= off) ? s_scan[tid - off] : 0;
    __syncthreads();
    s_scan[tid] += v;
    __syncthreads();
  }
  int incl = s_scan[tid];
  int excl = incl - local;
  if (tid == 1023) bc[2] = incl;            // total
  if (excl < k && k <= incl) {              // owner thread
    int c = excl;
    for (int i = 0; i < bpt; i++) {
      int h = (int)hist[base + i];
      if (c + h >= k) { bc[0] = base + i; bc[1] = c; break; }
      c += h;
    }
  }
  __syncthreads();
}

template<int CLS>
__device__ int subsample(int b, const unsigned int* marr, int k,
                         unsigned int* hist, int* s_scan, int* bc) {
  const unsigned char* lab = &g_label[(size_t)b * TT];
  const unsigned int*  mm  = &marr[(size_t)b * TT];
  signed char*         lf  = &g_labelf[(size_t)b * TT];
  int tid = threadIdx.x;

  for (int i = tid; i < 4096; i += 1024) hist[i] = 0u;
  __syncthreads();
  for (int t = tid; t < TT; t += 1024)
    if (lab[t] == CLS) atomicAdd(&hist[mm[t] >> 11], 1u);
  __syncthreads();
  kth_from_hist(hist, 4096, k, s_scan, bc);
  int n = bc[2];
  if (n <= k) return n;                     // keep all
  int cbin = bc[0], cumb = bc[1];

  // fine histogram within the coarse bin (low 11 bits -> exact 23-bit value)
  __syncthreads();
  for (int i = tid; i < 2048; i += 1024) hist[i] = 0u;
  __syncthreads();
  unsigned int cb = (unsigned int)cbin;
  for (int t = tid; t < TT; t += 1024) {
    if (lab[t] == CLS) {
      unsigned int m = mm[t];
      if ((m >> 11) == cb) atomicAdd(&hist[m & 2047u], 1u);
    }
  }
  __syncthreads();
  kth_from_hist(hist, 2048, k - cumb, s_scan, bc);
  int fbin = bc[0], fcumb = bc[1];
  unsigned int mstar = (cb << 11) | (unsigned int)fbin;
  int r = k - (cumb + fcumb);               // ties to keep (>=1)
  __syncthreads();

  // index-ordered tie resolution + demotion (stable argsort semantics)
  const int CH = (TT + 1023) / 1024;        // 57
  int t0 = tid * CH, t1 = min(TT, t0 + CH);
  int myt = 0;
  for (int t = t0; t < t1; t++)
    if (lab[t] == CLS && mm[t] == mstar) myt++;
  s_scan[tid] = myt; __syncthreads();
  for (int off = 1; off < 1024; off <<= 1) {
    int v = (tid >= off) ? s_scan[tid - off] : 0;
    __syncthreads();
    s_scan[tid] += v;
    __syncthreads();
  }
  int rank = s_scan[tid] - myt;             // exclusive prefix
  for (int t = t0; t < t1; t++) {
    if (lab[t] == CLS) {
      unsigned int m = mm[t];
      if (m > mstar) lf[t] = -1;
      else if (m == mstar) { if (rank >= r) lf[t] = -1; rank++; }
    }
  }
  __syncthreads();
  return k;
}

__global__ void __launch_bounds__(1024) k3_select() {
  __shared__ unsigned int hist[4096];
  __shared__ int s_scan[1024];
  __shared__ int bc[4];
  int b = blockIdx.x;
  int kept_fg = subsample<1>(b, g_mfg, FG_K, hist, s_scan, bc);
  __syncthreads();
  int kept_bg = subsample<0>(b, g_mbg, RPN_BATCH_K - kept_fg, hist, s_scan, bc);
  if (threadIdx.x == 0) g_uw[b] = 1.0f / (float)(kept_fg + kept_bg);
}

// ---------------- K4: write all four outputs ----------------
__global__ void k4_out(float* __restrict__ out) {
  int hw = blockIdx.x * 256 + threadIdx.x;   // 0..6399
  int b  = blockIdx.y;
  float u = g_uw[b];
  const size_t OFF1 = (size_t)BB * AA * HW;     // labels size
  const size_t PL   = (size_t)BB * 36 * HW;     // per-tensor size for the others
  float* lab_o  = out;
  float* tgt_o  = out + OFF1;
  float* inw_o  = out + OFF1 + PL;
  float* outw_o = out + OFF1 + 2*PL;
#pragma unroll
  for (int a = 0; a < AA; a++) {
    int t = hw * AA + a;
    size_t gi = (size_t)b * TT + t;
    signed char L = g_labelf[gi];
    float4 tg = g_targets[gi];
    lab_o[(size_t)b*AA*HW + (size_t)a*HW + hw] = (float)L;
    size_t cbase = (size_t)b*36*HW + (size_t)(a*4)*HW + hw;
    tgt_o[cbase        ] = tg.x;
    tgt_o[cbase +   HW ] = tg.y;
    tgt_o[cbase + 2*HW ] = tg.z;
    tgt_o[cbase + 3*HW ] = tg.w;
    float iw = (L == 1) ? 1.0f : 0.0f;
    float ow = (L >= 0) ? u : 0.0f;
    inw_o[cbase        ] = iw;
    inw_o[cbase +   HW ] = iw;
    inw_o[cbase + 2*HW ] = iw;
    inw_o[cbase + 3*HW ] = iw;
    outw_o[cbase        ] = ow;
    outw_o[cbase +   HW ] = ow;
    outw_o[cbase + 2*HW ] = ow;
    outw_o[cbase + 3*HW ] = ow;
  }
}

// ---------------- host ----------------
extern "C" void kernel_launch(void* const* d_in, const int* in_sizes, int n_in,
                              void* d_out, int out_size) {
  const float* gt     = (const float*)d_in[1];   // gt_boxes [32,20,5]
  const float* iminfo = (const float*)d_in[2];   // im_info [32,3]
  float* out = (float*)d_out;

  // JAX: key(42) -> split (partitionable/foldlike): kf = TF(key,(0,0)), kb = TF(key,(0,1))
  uint32_t kf0, kf1, kb0, kb1;
  tf2x32(0u, 42u, 0u, 0u, kf0, kf1);
  tf2x32(0u, 42u, 0u, 1u, kb0, kb1);

  k0_init<<<1, 640>>>();
  k1_gtmax<<<dim3(TT/256, BB), 256>>>(gt, iminfo);
  k2_main<<<dim3(TT/256, BB), 256>>>(gt, iminfo, kf0, kf1, kb0, kb1);
  k3_select<<<BB, 1024>>>();
  k4_out<<<dim3(HW/256, BB), 256>>>(out);
}

// round 2
// speedup vs baseline: 2.3244x; 2.3244x over previous
#include <cuda_runtime.h>
#include <stdint.h>

#define BB 32
#define NGT 20
#define FH 64
#define FW 100
#define AA 9
#define HW (FH*FW)      // 6400
#define TT (HW*AA)      // 57600
#define FG_K 128
#define RPN_BATCH_K 256
#define FULLM 0xffffffffu

__device__ __constant__ float c_anchors[AA*4] = {
  -84.f,  -40.f,  99.f,  55.f,
 -176.f,  -88.f, 191.f, 103.f,
 -360.f, -184.f, 375.f, 199.f,
  -56.f,  -56.f,  71.f,  71.f,
 -120.f, -120.f, 135.f, 135.f,
 -248.f, -248.f, 263.f, 263.f,
  -36.f,  -80.f,  51.f,  95.f,
  -80.f, -168.f,  95.f, 183.f,
 -168.f, -344.f, 183.f, 359.f
};

// ---------------- Threefry-2x32 (20 rounds), matches JAX partitionable ----------------
__host__ __device__ __forceinline__ void tf2x32(uint32_t k0, uint32_t k1,
                                                uint32_t x0, uint32_t x1,
                                                uint32_t& o0, uint32_t& o1) {
  uint32_t ks2 = k0 ^ k1 ^ 0x1BD11BDAu;
  x0 += k0; x1 += k1;
#define TF_RND(r) { x0 += x1; x1 = (x1 << (r)) | (x1 >> (32 - (r))); x1 ^= x0; }
  TF_RND(13) TF_RND(15) TF_RND(26) TF_RND(6)   x0 += k1;  x1 += ks2 + 1u;
  TF_RND(17) TF_RND(29) TF_RND(16) TF_RND(24)  x0 += ks2; x1 += k0  + 2u;
  TF_RND(13) TF_RND(15) TF_RND(26) TF_RND(6)   x0 += k0;  x1 += k1  + 3u;
  TF_RND(17) TF_RND(29) TF_RND(16) TF_RND(24)  x0 += k1;  x1 += ks2 + 4u;
  TF_RND(13) TF_RND(15) TF_RND(26) TF_RND(6)   x0 += ks2; x1 += k0  + 5u;
#undef TF_RND
  o0 = x0; o1 = x1;
}

// ---------------- scratch (device globals; no allocations) ----------------
struct ZeroBlk {
  unsigned int histfg[BB][4096];
  unsigned int histbg[BB][4096];
  unsigned int gtmax[BB*NGT];   // fordu-encoded positive-float max (0 = none)
};
__device__ ZeroBlk      g_z;
__device__ unsigned char g_lab[BB*TT];   // s = a*HW+hw order; 0=bg,1=fg,2=dontcare
__device__ unsigned int  g_mfg[BB*TT];   // written only where lab==1
__device__ unsigned int  g_mbg[BB*TT];   // written only where lab==0
__device__ float         g_uw[BB];

// ---------------- K0: zero the atomic scratch ----------------
__global__ void k0_zero() {
  unsigned* p = reinterpret_cast<unsigned*>(&g_z);
  const int N = (int)(sizeof(ZeroBlk) / 4);
  for (int i = blockIdx.x * 1024 + threadIdx.x; i < N; i += gridDim.x * 1024)
    p[i] = 0u;
}

// ---------------- K1: per-(b,g) max of positive IoUs ----------------
__global__ void k1_gtmax(const float* __restrict__ gt, const float* __restrict__ iminfo) {
  __shared__ float    s_gt[NGT*5];
  __shared__ unsigned s_max[NGT];
  int b = blockIdx.z, a = blockIdx.y, tid = threadIdx.x;
  int hw = blockIdx.x * 256 + tid;
  if (tid < NGT*5) s_gt[tid] = gt[b*NGT*5 + tid];
  if (tid < NGT)   s_max[tid] = 0u;
  __syncthreads();
  float img_h = iminfo[0], img_w = iminfo[1];
  int h = hw / FW, w = hw - h * FW;
  float sx = (float)(w * 16), sy = (float)(h * 16);
  float ax1 = c_anchors[a*4+0] + sx;
  float ay1 = c_anchors[a*4+1] + sy;
  float ax2 = c_anchors[a*4+2] + sx;
  float ay2 = c_anchors[a*4+3] + sy;
  bool inside = (ax1 >= 0.f) && (ay1 >= 0.f) && (ax2 < img_w) && (ay2 < img_h);
  float aw = __fadd_rn(__fsub_rn(ax2, ax1), 1.0f);
  float ah = __fadd_rn(__fsub_rn(ay2, ay1), 1.0f);
  float area = __fmul_rn(aw, ah);

  if (__ballot_sync(FULLM, inside)) {
    for (int g = 0; g < NGT; g++) {
      float gx1 = s_gt[g*5+0], gy1 = s_gt[g*5+1], gx2 = s_gt[g*5+2], gy2 = s_gt[g*5+3];
      float gw = __fadd_rn(__fsub_rn(gx2, gx1), 1.0f);
      float gh = __fadd_rn(__fsub_rn(gy2, gy1), 1.0f);
      bool gz = (gw == 1.0f) && (gh == 1.0f);
      float iw = __fadd_rn(__fsub_rn(fminf(ax2, gx2), fmaxf(ax1, gx1)), 1.0f);
      float ih = __fadd_rn(__fsub_rn(fminf(ay2, gy2), fmaxf(ay1, gy1)), 1.0f);
      float inter = __fmul_rn(fmaxf(iw, 0.0f), fmaxf(ih, 0.0f));
      bool need = inside && !gz && (inter > 0.0f);
      if (__ballot_sync(FULLM, need)) {
        unsigned fu = 0u;
        if (need) {
          float ga = __fmul_rn(gw, gh);
          float ua = __fsub_rn(__fadd_rn(area, ga), inter);
          float v  = __fdiv_rn(inter, ua);           // > 0
          fu = __float_as_uint(v) | 0x80000000u;     // order-preserving for positives
        }
        unsigned r = __reduce_max_sync(FULLM, fu);
        if ((tid & 31) == 0) atomicMax(&s_max[g], r);
      }
    }
  }
  __syncthreads();
  if (tid < NGT && s_max[tid]) atomicMax(&g_z.gtmax[b*NGT + tid], s_max[tid]);
}

// ---------------- K2: labels, targets -> out, RNG draws + histograms ----------------
__global__ void k2_main(const float* __restrict__ gt, const float* __restrict__ iminfo,
                        uint32_t kf0, uint32_t kf1, uint32_t kb0, uint32_t kb1,
                        float* __restrict__ out) {
  __shared__ float s_gt[NGT*5];
  __shared__ float s_gm[NGT];
  int b = blockIdx.z, a = blockIdx.y, tid = threadIdx.x;
  int hw = blockIdx.x * 256 + tid;
  if (tid < NGT*5) s_gt[tid] = gt[b*NGT*5 + tid];
  if (tid < NGT) {
    unsigned u_ = g_z.gtmax[b*NGT + tid];
    // decode positive float; 0 => no positive candidate => sentinel never matched
    s_gm[tid] = u_ ? __uint_as_float(u_ ^ 0x80000000u) : -999.0f;
  }
  __syncthreads();
  float img_h = iminfo[0], img_w = iminfo[1];
  int h = hw / FW, w = hw - h * FW;
  float sx = (float)(w * 16), sy = (float)(h * 16);
  float ax1 = c_anchors[a*4+0] + sx;
  float ay1 = c_anchors[a*4+1] + sy;
  float ax2 = c_anchors[a*4+2] + sx;
  float ay2 = c_anchors[a*4+3] + sy;
  bool inside = (ax1 >= 0.f) && (ay1 >= 0.f) && (ax2 < img_w) && (ay2 < img_h);
  float aw = __fadd_rn(__fsub_rn(ax2, ax1), 1.0f);
  float ah = __fadd_rn(__fsub_rn(ay2, ay1), 1.0f);
  float area = __fmul_rn(aw, ah);

  float mx = -3.0f; int amax = 0; bool keep = false;
  if (__ballot_sync(FULLM, inside)) {
    for (int g = 0; g < NGT; g++) {
      float gx1 = s_gt[g*5+0], gy1 = s_gt[g*5+1], gx2 = s_gt[g*5+2], gy2 = s_gt[g*5+3];
      float gw = __fadd_rn(__fsub_rn(gx2, gx1), 1.0f);
      float gh = __fadd_rn(__fsub_rn(gy2, gy1), 1.0f);
      bool gz = (gw == 1.0f) && (gh == 1.0f);
      float iw = __fadd_rn(__fsub_rn(fminf(ax2, gx2), fmaxf(ax1, gx1)), 1.0f);
      float ih = __fadd_rn(__fsub_rn(fminf(ay2, gy2), fmaxf(ay1, gy1)), 1.0f);
      float inter = __fmul_rn(fmaxf(iw, 0.0f), fmaxf(ih, 0.0f));
      bool need = inside && !gz && (inter > 0.0f);
      float v = 0.0f;
      if (__ballot_sync(FULLM, need)) {
        if (need) {
          float ga = __fmul_rn(gw, gh);
          float ua = __fsub_rn(__fadd_rn(area, ga), inter);
          v = __fdiv_rn(inter, ua);
        }
      }
      keep = keep || (v == s_gm[g]);
      if (v > mx) { mx = v; amax = g; }   // first-occurrence argmax
    }
  }

  unsigned char L = 2;
  if (inside) L = (keep || mx >= 0.7f) ? 1 : ((mx < 0.3f) ? 0 : 2);
  size_t sidx = (size_t)b * TT + a * HW + hw;
  g_lab[sidx] = L;

  // bbox targets straight into output (coalesced planes)
  float4 tg = make_float4(0.f, 0.f, 0.f, 0.f);
  if (inside) {
    const float* g5 = &s_gt[amax*5];
    float ew = ax2 - ax1 + 1.0f, eh = ay2 - ay1 + 1.0f;
    float ecx = ax1 + 0.5f*ew,   ecy = ay1 + 0.5f*eh;
    float gw = g5[2] - g5[0] + 1.0f, gh = g5[3] - g5[1] + 1.0f;
    float gcx = g5[0] + 0.5f*gw,     gcy = g5[1] + 0.5f*gh;
    tg.x = (gcx - ecx) / ew;
    tg.y = (gcy - ecy) / eh;
    tg.z = logf(gw / ew);
    tg.w = logf(gh / eh);
  }
  float* tgt_o = out + (size_t)BB * AA * HW;
  size_t cb = ((size_t)b * 36 + a * 4) * HW + hw;
  tgt_o[cb         ] = tg.x;
  tgt_o[cb +   HW  ] = tg.y;
  tgt_o[cb + 2*HW  ] = tg.z;
  tgt_o[cb + 3*HW  ] = tg.w;

  // one threefry per needed lane, key selected per-lane (no divergence)
  if (__ballot_sync(FULLM, L <= 1)) {
    if (L <= 1) {
      uint32_t key0 = L ? kf0 : kb0, key1 = L ? kf1 : kb1;
      uint32_t o0, o1;
      uint32_t cnt = (uint32_t)(b * TT + hw * 9 + a);   // original t-order counter
      tf2x32(key0, key1, 0u, cnt, o0, o1);
      unsigned m = (o0 ^ o1) >> 9;                      // 23-bit, monotone in uniform
      if (L) { g_mfg[sidx] = m; atomicAdd(&g_z.histfg[b][m >> 11], 1u); }
      else   { g_mbg[sidx] = m; atomicAdd(&g_z.histbg[b][m >> 11], 1u); }
    }
  }
}

// ---------------- K3: per-(batch,class) k-smallest selection ----------------
__device__ __forceinline__ int blockInclScan(int local, int* s_wsum) {
  int lane = threadIdx.x & 31, wid = threadIdx.x >> 5;
  int v = local;
#pragma unroll
  for (int o = 1; o < 32; o <<= 1) { int n = __shfl_up_sync(FULLM, v, o); if (lane >= o) v += n; }
  if (lane == 31) s_wsum[wid] = v;
  __syncthreads();
  if (wid == 0) {
    int wv = s_wsum[lane];
#pragma unroll
    for (int o = 1; o < 32; o <<= 1) { int n = __shfl_up_sync(FULLM, wv, o); if (lane >= o) wv += n; }
    s_wsum[lane] = wv;
  }
  __syncthreads();
  return v + (wid ? s_wsum[wid-1] : 0);
}

// finds bin containing the k-th smallest; s_bc = {bin, cumBefore, total}
__device__ void kth(const unsigned* hist, int bpt, int k, int* s_wsum, int* s_bc) {
  int tid = threadIdx.x;
  int base = tid * bpt;
  int local = 0;
  for (int i = 0; i < bpt; i++) local += (int)hist[base + i];
  int incl = blockInclScan(local, s_wsum);
  if (tid == 1023) s_bc[2] = incl;
  int excl = incl - local;
  if (k > excl && k <= incl) {
    int c = excl;
    for (int i = 0; i < bpt; i++) {
      int hh = (int)hist[base + i];
      if (c + hh >= k) { s_bc[0] = base + i; s_bc[1] = c; break; }
      c += hh;
    }
  }
  __syncthreads();
}

__global__ void __launch_bounds__(1024) k3_select() {
  __shared__ unsigned s_fine[2048];
  __shared__ int s_wsum[32];
  __shared__ int s_bc[3];
  __shared__ int s_list[512];
  __shared__ int s_cnt;
  __shared__ int s_nfg;
  int b = blockIdx.x, cls = blockIdx.y, tid = threadIdx.x;
  int lane = tid & 31, wid = tid >> 5;

  const unsigned* chist = cls ? g_z.histfg[b] : g_z.histbg[b];
  const unsigned* mm = (cls ? g_mfg : g_mbg) + (size_t)b * TT;
  unsigned char*  lab = g_lab + (size_t)b * TT;

  int k;
  if (cls) {
    k = FG_K;
  } else {
    // nfg = sum of fg hist (cheap)
    const unsigned* fh = g_z.histfg[b];
    int loc = 0;
    for (int i = tid; i < 4096; i += 1024) loc += (int)fh[i];
    loc = __reduce_add_sync(FULLM, loc);
    if (lane == 0) s_wsum[wid] = loc;
    __syncthreads();
    if (tid == 0) { int s = 0; for (int i = 0; i < 32; i++) s += s_wsum[i]; s_nfg = s; }
    __syncthreads();
    k = RPN_BATCH_K - min(s_nfg, FG_K);
  }
  __syncthreads();

  kth(chist, 4, k, s_wsum, s_bc);
  int n = s_bc[2];
  if (n <= k) {
    if (cls == 0 && tid == 0)
      g_uw[b] = 1.0f / (float)(min(s_nfg, FG_K) + n);
    return;
  }
  if (cls == 0 && tid == 0)
    g_uw[b] = 1.0f / (float)(min(s_nfg, FG_K) + k);
  int cbin = s_bc[0], cum = s_bc[1];

  // fine histogram within coarse bin (low 11 bits)
  for (int i = tid; i < 2048; i += 1024) s_fine[i] = 0u;
  if (tid == 0) s_cnt = 0;
  __syncthreads();
  for (int s = tid; s < TT; s += 1024) {
    if (lab[s] == cls) {
      unsigned m = mm[s];
      if ((int)(m >> 11) == cbin) atomicAdd(&s_fine[m & 2047u], 1u);
    }
  }
  __syncthreads();
  kth(s_fine, 2, k - cum, s_wsum, s_bc);
  int fbin = s_bc[0], fcum = s_bc[1];
  unsigned mstar = ((unsigned)cbin << 11) | (unsigned)fbin;
  int r = k - cum - fcum;      // >= 1 : how many ties (lowest original t) to keep
  __syncthreads();

  // demote pass + collect ties
  for (int s = tid; s < TT; s += 1024) {
    if (lab[s] == cls) {
      unsigned m = mm[s];
      if (m > mstar) lab[s] = 2;
      else if (m == mstar) {
        int i = atomicAdd(&s_cnt, 1);
        if (i < 512) s_list[i] = (s % HW) * 9 + (s / HW);  // original t
      }
    }
  }
  __syncthreads();
  if (tid == 0) {
    int n2 = min(s_cnt, 512);
    for (int i = 1; i < n2; i++) {           // insertion sort ascending by t
      int v = s_list[i], j = i - 1;
      while (j >= 0 && s_list[j] > v) { s_list[j+1] = s_list[j]; j--; }
      s_list[j+1] = v;
    }
    for (int i = r; i < n2; i++) {           // keep r smallest-t ties, demote rest
      int t = s_list[i];
      lab[(t % 9) * HW + t / 9] = 2;
    }
  }
}

// ---------------- K4: labels + in/out weights (vectorized) ----------------
__global__ void k4_out(float* __restrict__ out) {
  int idx = blockIdx.x * 320 + threadIdx.x;   // 0..1599
  int b = blockIdx.y;
  int hw = idx * 4;
  float u = g_uw[b];
  const size_t OFF1 = (size_t)BB * AA * HW;
  const size_t PL   = (size_t)BB * 36 * HW;
  float* lab_o  = out;
  float* inw_o  = out + OFF1 + PL;
  float* outw_o = out + OFF1 + 2 * PL;
#pragma unroll
  for (int a = 0; a < AA; a++) {
    uchar4 L4 = *reinterpret_cast<const uchar4*>(&g_lab[(size_t)b * TT + a * HW + hw]);
    float4 lv, iw, ow;
    lv.x = (L4.x == 2) ? -1.f : (float)L4.x;
    lv.y = (L4.y == 2) ? -1.f : (float)L4.y;
    lv.z = (L4.z == 2) ? -1.f : (float)L4.z;
    lv.w = (L4.w == 2) ? -1.f : (float)L4.w;
    iw.x = (L4.x == 1) ? 1.f : 0.f;
    iw.y = (L4.y == 1) ? 1.f : 0.f;
    iw.z = (L4.z == 1) ? 1.f : 0.f;
    iw.w = (L4.w == 1) ? 1.f : 0.f;
    ow.x = (L4.x != 2) ? u : 0.f;
    ow.y = (L4.y != 2) ? u : 0.f;
    ow.z = (L4.z != 2) ? u : 0.f;
    ow.w = (L4.w != 2) ? u : 0.f;
    *reinterpret_cast<float4*>(&lab_o[((size_t)b * AA + a) * HW + hw]) = lv;
    size_t cbase = ((size_t)b * 36 + a * 4) * HW + hw;
#pragma unroll
    for (int c = 0; c < 4; c++) {
      *reinterpret_cast<float4*>(&inw_o [cbase + (size_t)c * HW]) = iw;
      *reinterpret_cast<float4*>(&outw_o[cbase + (size_t)c * HW]) = ow;
    }
  }
}

// ---------------- host ----------------
extern "C" void kernel_launch(void* const* d_in, const int* in_sizes, int n_in,
                              void* d_out, int out_size) {
  const float* gt     = (const float*)d_in[1];   // gt_boxes [32,20,5]
  const float* iminfo = (const float*)d_in[2];   // im_info [32,3]
  float* out = (float*)d_out;

  // JAX split(key(42)) partitionable: kf = TF([0,42],(0,0)), kb = TF([0,42],(0,1))
  uint32_t kf0, kf1, kb0, kb1;
  tf2x32(0u, 42u, 0u, 0u, kf0, kf1);
  tf2x32(0u, 42u, 0u, 1u, kb0, kb1);

  k0_zero  <<<64, 1024>>>();
  k1_gtmax <<<dim3(HW/256, AA, BB), 256>>>(gt, iminfo);
  k2_main  <<<dim3(HW/256, AA, BB), 256>>>(gt, iminfo, kf0, kf1, kb0, kb1, out);
  k3_select<<<dim3(BB, 2), 1024>>>();
  k4_out   <<<dim3(5, BB), 320>>>(out);
}

// round 3
// speedup vs baseline: 2.3562x; 1.0137x over previous
#include <cuda_runtime.h>
#include <stdint.h>

#define BB 32
#define NGT 20
#define FH 64
#define FW 100
#define AA 9
#define HW (FH*FW)      // 6400
#define TT (HW*AA)      // 57600
#define FG_K 128
#define RPN_BATCH_K 256
#define FULLM 0xffffffffu

__device__ __constant__ float c_anchors[AA*4] = {
  -84.f,  -40.f,  99.f,  55.f,
 -176.f,  -88.f, 191.f, 103.f,
 -360.f, -184.f, 375.f, 199.f,
  -56.f,  -56.f,  71.f,  71.f,
 -120.f, -120.f, 135.f, 135.f,
 -248.f, -248.f, 263.f, 263.f,
  -36.f,  -80.f,  51.f,  95.f,
  -80.f, -168.f,  95.f, 183.f,
 -168.f, -344.f, 183.f, 359.f
};

// ---------------- Threefry-2x32 (20 rounds), matches JAX partitionable ----------------
__host__ __device__ __forceinline__ void tf2x32(uint32_t k0, uint32_t k1,
                                                uint32_t x0, uint32_t x1,
                                                uint32_t& o0, uint32_t& o1) {
  uint32_t ks2 = k0 ^ k1 ^ 0x1BD11BDAu;
  x0 += k0; x1 += k1;
#define TF_RND(r) { x0 += x1; x1 = (x1 << (r)) | (x1 >> (32 - (r))); x1 ^= x0; }
  TF_RND(13) TF_RND(15) TF_RND(26) TF_RND(6)   x0 += k1;  x1 += ks2 + 1u;
  TF_RND(17) TF_RND(29) TF_RND(16) TF_RND(24)  x0 += ks2; x1 += k0  + 2u;
  TF_RND(13) TF_RND(15) TF_RND(26) TF_RND(6)   x0 += k0;  x1 += k1  + 3u;
  TF_RND(17) TF_RND(29) TF_RND(16) TF_RND(24)  x0 += k1;  x1 += ks2 + 4u;
  TF_RND(13) TF_RND(15) TF_RND(26) TF_RND(6)   x0 += ks2; x1 += k0  + 5u;
#undef TF_RND
  o0 = x0; o1 = x1;
}

// ---------------- scratch (device globals; no allocations) ----------------
__device__ unsigned int        g_gtmax[BB*NGT];  // biased-float max of positive IoUs (0 = none)
__device__ int                 g_cnt_fg[BB];
__device__ int                 g_cnt_bg[BB];
__device__ unsigned char       g_lab[BB*TT];     // s = a*HW+hw order; 0=bg,1=fg,2=dontcare
__device__ unsigned long long  g_cfg[(size_t)BB*TT];  // fg candidate keys (m<<16)|t
__device__ unsigned long long  g_cbg[(size_t)BB*TT];  // bg candidate keys
__device__ float               g_uw[BB];

// ---------------- K0: zero tiny scratch ----------------
__global__ void k0_zero() {
  int i = threadIdx.x;
  if (i < BB*NGT) g_gtmax[i] = 0u;
  if (i < BB) { g_cnt_fg[i] = 0; g_cnt_bg[i] = 0; }
}

// ---------------- K1: per-(b,g) max of positive IoUs ----------------
__global__ void k1_gtmax(const float* __restrict__ gt, const float* __restrict__ iminfo) {
  __shared__ float    s_gt[NGT*5];
  __shared__ unsigned s_max[NGT];
  int b = blockIdx.z, a = blockIdx.y, tid = threadIdx.x;
  int hw = blockIdx.x * 256 + tid;
  if (tid < NGT*5) s_gt[tid] = gt[b*NGT*5 + tid];
  if (tid < NGT)   s_max[tid] = 0u;
  __syncthreads();
  float img_h = iminfo[0], img_w = iminfo[1];
  int h = hw / FW, w = hw - h * FW;
  float sx = (float)(w * 16), sy = (float)(h * 16);
  float ax1 = c_anchors[a*4+0] + sx;
  float ay1 = c_anchors[a*4+1] + sy;
  float ax2 = c_anchors[a*4+2] + sx;
  float ay2 = c_anchors[a*4+3] + sy;
  bool inside = (ax1 >= 0.f) && (ay1 >= 0.f) && (ax2 < img_w) && (ay2 < img_h);
  float aw = __fadd_rn(__fsub_rn(ax2, ax1), 1.0f);
  float ah = __fadd_rn(__fsub_rn(ay2, ay1), 1.0f);
  float area = __fmul_rn(aw, ah);

  if (__ballot_sync(FULLM, inside)) {
    for (int g = 0; g < NGT; g++) {
      float gx1 = s_gt[g*5+0], gy1 = s_gt[g*5+1], gx2 = s_gt[g*5+2], gy2 = s_gt[g*5+3];
      float gw = __fadd_rn(__fsub_rn(gx2, gx1), 1.0f);
      float gh = __fadd_rn(__fsub_rn(gy2, gy1), 1.0f);
      bool gz = (gw == 1.0f) && (gh == 1.0f);
      float iw = __fadd_rn(__fsub_rn(fminf(ax2, gx2), fmaxf(ax1, gx1)), 1.0f);
      float ih = __fadd_rn(__fsub_rn(fminf(ay2, gy2), fmaxf(ay1, gy1)), 1.0f);
      float inter = __fmul_rn(fmaxf(iw, 0.0f), fmaxf(ih, 0.0f));
      bool need = inside && !gz && (inter > 0.0f);
      if (__ballot_sync(FULLM, need)) {
        unsigned fu = 0u;
        if (need) {
          float ga = __fmul_rn(gw, gh);
          float ua = __fsub_rn(__fadd_rn(area, ga), inter);
          float v  = __fdiv_rn(inter, ua);           // > 0
          fu = __float_as_uint(v) | 0x80000000u;     // order-preserving for positives
        }
        unsigned r = __reduce_max_sync(FULLM, fu);
        if ((tid & 31) == 0) atomicMax(&s_max[g], r);
      }
    }
  }
  __syncthreads();
  if (tid < NGT && s_max[tid]) atomicMax(&g_gtmax[b*NGT + tid], s_max[tid]);
}

// ---------------- K2: labels, targets -> out, RNG + compaction ----------------
__global__ void k2_main(const float* __restrict__ gt, const float* __restrict__ iminfo,
                        uint32_t kf0, uint32_t kf1, uint32_t kb0, uint32_t kb1,
                        float* __restrict__ out) {
  __shared__ float s_gt[NGT*5];
  __shared__ float s_gm[NGT];
  int b = blockIdx.z, a = blockIdx.y, tid = threadIdx.x;
  int hw = blockIdx.x * 256 + tid;
  if (tid < NGT*5) s_gt[tid] = gt[b*NGT*5 + tid];
  if (tid < NGT) {
    unsigned u_ = g_gtmax[b*NGT + tid];
    s_gm[tid] = u_ ? __uint_as_float(u_ ^ 0x80000000u) : -999.0f;
  }
  __syncthreads();
  float img_h = iminfo[0], img_w = iminfo[1];
  int h = hw / FW, w = hw - h * FW;
  float sx = (float)(w * 16), sy = (float)(h * 16);
  float ax1 = c_anchors[a*4+0] + sx;
  float ay1 = c_anchors[a*4+1] + sy;
  float ax2 = c_anchors[a*4+2] + sx;
  float ay2 = c_anchors[a*4+3] + sy;
  bool inside = (ax1 >= 0.f) && (ay1 >= 0.f) && (ax2 < img_w) && (ay2 < img_h);
  float aw = __fadd_rn(__fsub_rn(ax2, ax1), 1.0f);
  float ah = __fadd_rn(__fsub_rn(ay2, ay1), 1.0f);
  float area = __fmul_rn(aw, ah);

  float mx = -3.0f; int amax = 0; bool keep = false;
  if (__ballot_sync(FULLM, inside)) {
    for (int g = 0; g < NGT; g++) {
      float gx1 = s_gt[g*5+0], gy1 = s_gt[g*5+1], gx2 = s_gt[g*5+2], gy2 = s_gt[g*5+3];
      float gw = __fadd_rn(__fsub_rn(gx2, gx1), 1.0f);
      float gh = __fadd_rn(__fsub_rn(gy2, gy1), 1.0f);
      bool gz = (gw == 1.0f) && (gh == 1.0f);
      float iw = __fadd_rn(__fsub_rn(fminf(ax2, gx2), fmaxf(ax1, gx1)), 1.0f);
      float ih = __fadd_rn(__fsub_rn(fminf(ay2, gy2), fmaxf(ay1, gy1)), 1.0f);
      float inter = __fmul_rn(fmaxf(iw, 0.0f), fmaxf(ih, 0.0f));
      bool need = inside && !gz && (inter > 0.0f);
      float v = 0.0f;
      if (__ballot_sync(FULLM, need)) {
        if (need) {
          float ga = __fmul_rn(gw, gh);
          float ua = __fsub_rn(__fadd_rn(area, ga), inter);
          v = __fdiv_rn(inter, ua);
        }
      }
      keep = keep || (v == s_gm[g]);
      if (v > mx) { mx = v; amax = g; }   // first-occurrence argmax
    }
  }

  unsigned char L = 2;
  if (inside) L = (keep || mx >= 0.7f) ? 1 : ((mx < 0.3f) ? 0 : 2);
  size_t sidx = (size_t)b * TT + a * HW + hw;
  g_lab[sidx] = L;

  // bbox targets straight into output (coalesced planes)
  float4 tg = make_float4(0.f, 0.f, 0.f, 0.f);
  if (inside) {
    const float* g5 = &s_gt[amax*5];
    float ew = ax2 - ax1 + 1.0f, eh = ay2 - ay1 + 1.0f;
    float ecx = ax1 + 0.5f*ew,   ecy = ay1 + 0.5f*eh;
    float gw = g5[2] - g5[0] + 1.0f, gh = g5[3] - g5[1] + 1.0f;
    float gcx = g5[0] + 0.5f*gw,     gcy = g5[1] + 0.5f*gh;
    tg.x = (gcx - ecx) / ew;
    tg.y = (gcy - ecy) / eh;
    tg.z = logf(gw / ew);
    tg.w = logf(gh / eh);
  }
  float* tgt_o = out + (size_t)BB * AA * HW;
  size_t cb = ((size_t)b * 36 + a * 4) * HW + hw;
  tgt_o[cb        ] = tg.x;
  tgt_o[cb +   HW ] = tg.y;
  tgt_o[cb + 2*HW ] = tg.z;
  tgt_o[cb + 3*HW ] = tg.w;

  // RNG draw + warp-aggregated compaction of candidate keys
  unsigned ballot_fg = __ballot_sync(FULLM, L == 1);
  unsigned ballot_bg = __ballot_sync(FULLM, L == 0);
  unsigned long long key = 0ull;
  int t = hw * 9 + a;                      // original anchor index (t-order)
  if (L <= 1) {
    uint32_t key0 = L ? kf0 : kb0, key1 = L ? kf1 : kb1;
    uint32_t o0, o1;
    uint32_t cnt = (uint32_t)(b * TT + t);
    tf2x32(key0, key1, 0u, cnt, o0, o1);
    unsigned m = (o0 ^ o1) >> 9;           // 23-bit, monotone in uniform
    key = ((unsigned long long)m << 16) | (unsigned)t;   // unique 39-bit key
  }
  int lane = tid & 31;
  if (L == 1) {
    unsigned mask = ballot_fg;
    int leader = __ffs(mask) - 1;
    int base = 0;
    if (lane == leader) base = atomicAdd(&g_cnt_fg[b], __popc(mask));
    base = __shfl_sync(mask, base, leader);
    int off = __popc(mask & ((1u << lane) - 1u));
    g_cfg[(size_t)b * TT + base + off] = key;
  } else if (L == 0) {
    unsigned mask = ballot_bg;
    int leader = __ffs(mask) - 1;
    int base = 0;
    if (lane == leader) base = atomicAdd(&g_cnt_bg[b], __popc(mask));
    base = __shfl_sync(mask, base, leader);
    int off = __popc(mask & ((1u << lane) - 1u));
    g_cbg[(size_t)b * TT + base + off] = key;
  }
}

// ---------------- K3: exact radix select on 39-bit keys ----------------
__device__ __forceinline__ int blockInclScan(int local, int* s_wsum) {
  int lane = threadIdx.x & 31, wid = threadIdx.x >> 5;
  int v = local;
#pragma unroll
  for (int o = 1; o < 32; o <<= 1) { int n = __shfl_up_sync(FULLM, v, o); if (lane >= o) v += n; }
  if (lane == 31) s_wsum[wid] = v;
  __syncthreads();
  if (wid == 0) {
    int wv = s_wsum[lane];
#pragma unroll
    for (int o = 1; o < 32; o <<= 1) { int n = __shfl_up_sync(FULLM, wv, o); if (lane >= o) wv += n; }
    s_wsum[lane] = wv;
  }
  __syncthreads();
  return v + (wid ? s_wsum[wid-1] : 0);
}

__global__ void __launch_bounds__(1024) k3_select() {
  __shared__ unsigned s_hist[8192];
  __shared__ int s_wsum[32];
  __shared__ int s_sel[2];   // {bin, cumBefore}
  int b = blockIdx.x, cls = blockIdx.y, tid = threadIdx.x;

  int nfg = g_cnt_fg[b];
  int n   = cls ? nfg : g_cnt_bg[b];
  int kept_fg = min(nfg, FG_K);
  int k = cls ? FG_K : (RPN_BATCH_K - kept_fg);
  if (cls == 0 && tid == 0)
    g_uw[b] = 1.0f / (float)(kept_fg + min(n, k));
  if (n <= k) return;

  const unsigned long long* keys = (cls ? g_cfg : g_cbg) + (size_t)b * TT;
  unsigned char* lab = g_lab + (size_t)b * TT;

  unsigned long long prefix = 0ull;
  int kk = k;
#pragma unroll
  for (int lvl = 0; lvl < 3; lvl++) {
    int shift = 26 - 13 * lvl;
    for (int i = tid; i < 8192; i += 1024) s_hist[i] = 0u;
    __syncthreads();
    for (int i = tid; i < n; i += 1024) {
      unsigned long long key = keys[i];
      if (lvl == 0 || (key >> (shift + 13)) == prefix)
        atomicAdd(&s_hist[(unsigned)(key >> shift) & 8191u], 1u);
    }
    __syncthreads();
    int base = tid * 8;
    int local = 0;
#pragma unroll
    for (int j = 0; j < 8; j++) local += (int)s_hist[base + j];
    int incl = blockInclScan(local, s_wsum);
    int excl = incl - local;
    if (kk > excl && kk <= incl) {
      int c = excl;
      for (int j = 0; j < 8; j++) {
        int hh = (int)s_hist[base + j];
        if (c + hh >= kk) { s_sel[0] = base + j; s_sel[1] = c; break; }
        c += hh;
      }
    }
    __syncthreads();
    prefix = (prefix << 13) | (unsigned)s_sel[0];
    kk -= s_sel[1];
    __syncthreads();
  }
  unsigned long long kstar = prefix;   // exact k-th smallest key (keys unique)

  // demote everything above the threshold
  for (int i = tid; i < n; i += 1024) {
    unsigned long long key = keys[i];
    if (key > kstar) {
      int t = (int)(key & 0xFFFFull);
      lab[(t % 9) * HW + t / 9] = 2;
    }
  }
}

// ---------------- K4: labels + in/out weights (vectorized) ----------------
__global__ void k4_out(float* __restrict__ out) {
  int idx = blockIdx.x * 320 + threadIdx.x;   // 0..1599
  int b = blockIdx.y;
  int hw = idx * 4;
  float u = g_uw[b];
  const size_t OFF1 = (size_t)BB * AA * HW;
  const size_t PL   = (size_t)BB * 36 * HW;
  float* lab_o  = out;
  float* inw_o  = out + OFF1 + PL;
  float* outw_o = out + OFF1 + 2 * PL;
#pragma unroll
  for (int a = 0; a < AA; a++) {
    uchar4 L4 = *reinterpret_cast<const uchar4*>(&g_lab[(size_t)b * TT + a * HW + hw]);
    float4 lv, iw, ow;
    lv.x = (L4.x == 2) ? -1.f : (float)L4.x;
    lv.y = (L4.y == 2) ? -1.f : (float)L4.y;
    lv.z = (L4.z == 2) ? -1.f : (float)L4.z;
    lv.w = (L4.w == 2) ? -1.f : (float)L4.w;
    iw.x = (L4.x == 1) ? 1.f : 0.f;
    iw.y = (L4.y == 1) ? 1.f : 0.f;
    iw.z = (L4.z == 1) ? 1.f : 0.f;
    iw.w = (L4.w == 1) ? 1.f : 0.f;
    ow.x = (L4.x != 2) ? u : 0.f;
    ow.y = (L4.y != 2) ? u : 0.f;
    ow.z = (L4.z != 2) ? u : 0.f;
    ow.w = (L4.w != 2) ? u : 0.f;
    *reinterpret_cast<float4*>(&lab_o[((size_t)b * AA + a) * HW + hw]) = lv;
    size_t cbase = ((size_t)b * 36 + a * 4) * HW + hw;
#pragma unroll
    for (int c = 0; c < 4; c++) {
      *reinterpret_cast<float4*>(&inw_o [cbase + (size_t)c * HW]) = iw;
      *reinterpret_cast<float4*>(&outw_o[cbase + (size_t)c * HW]) = ow;
    }
  }
}

// ---------------- host ----------------
extern "C" void kernel_launch(void* const* d_in, const int* in_sizes, int n_in,
                              void* d_out, int out_size) {
  const float* gt     = (const float*)d_in[1];   // gt_boxes [32,20,5]
  const float* iminfo = (const float*)d_in[2];   // im_info [32,3]
  float* out = (float*)d_out;

  uint32_t kf0, kf1, kb0, kb1;
  tf2x32(0u, 42u, 0u, 0u, kf0, kf1);
  tf2x32(0u, 42u, 0u, 1u, kb0, kb1);

  k0_zero  <<<1, 1024>>>();
  k1_gtmax <<<dim3(HW/256, AA, BB), 256>>>(gt, iminfo);
  k2_main  <<<dim3(HW/256, AA, BB), 256>>>(gt, iminfo, kf0, kf1, kb0, kb1, out);
  k3_select<<<dim3(BB, 2), 1024>>>();
  k4_out   <<<dim3(5, BB), 320>>>(out);
}

// round 4
// speedup vs baseline: 2.3625x; 1.0027x over previous
#include <cuda_runtime.h>
#include <stdint.h>

#define BB 32
#define NGT 20
#define FH 64
#define FW 100
#define AA 9
#define HW (FH*FW)      // 6400
#define TT (HW*AA)      // 57600
#define FG_K 128
#define RPN_BATCH_K 256
#define FULLM 0xffffffffu

__device__ __constant__ float c_anchors[AA*4] = {
  -84.f,  -40.f,  99.f,  55.f,
 -176.f,  -88.f, 191.f, 103.f,
 -360.f, -184.f, 375.f, 199.f,
  -56.f,  -56.f,  71.f,  71.f,
 -120.f, -120.f, 135.f, 135.f,
 -248.f, -248.f, 263.f, 263.f,
  -36.f,  -80.f,  51.f,  95.f,
  -80.f, -168.f,  95.f, 183.f,
 -168.f, -344.f, 183.f, 359.f
};

// ---------------- Threefry-2x32 (20 rounds), matches JAX partitionable ----------------
__host__ __device__ __forceinline__ void tf2x32(uint32_t k0, uint32_t k1,
                                                uint32_t x0, uint32_t x1,
                                                uint32_t& o0, uint32_t& o1) {
  uint32_t ks2 = k0 ^ k1 ^ 0x1BD11BDAu;
  x0 += k0; x1 += k1;
#define TF_RND(r) { x0 += x1; x1 = (x1 << (r)) | (x1 >> (32 - (r))); x1 ^= x0; }
  TF_RND(13) TF_RND(15) TF_RND(26) TF_RND(6)   x0 += k1;  x1 += ks2 + 1u;
  TF_RND(17) TF_RND(29) TF_RND(16) TF_RND(24)  x0 += ks2; x1 += k0  + 2u;
  TF_RND(13) TF_RND(15) TF_RND(26) TF_RND(6)   x0 += k0;  x1 += k1  + 3u;
  TF_RND(17) TF_RND(29) TF_RND(16) TF_RND(24)  x0 += k1;  x1 += ks2 + 4u;
  TF_RND(13) TF_RND(15) TF_RND(26) TF_RND(6)   x0 += ks2; x1 += k0  + 5u;
#undef TF_RND
  o0 = x0; o1 = x1;
}

// ---------------- scratch (device globals; no allocations) ----------------
__device__ unsigned int        g_gtmax[BB*NGT];  // biased-float max of positive IoUs (0 = none)
__device__ int                 g_cnt_fg[BB];
__device__ int                 g_cnt_bg[BB];
__device__ unsigned char       g_lab[BB*TT];     // s = a*HW+hw order; 0=bg,1=fg,2=dontcare
__device__ unsigned long long  g_cfg[(size_t)BB*TT];  // fg candidate keys (m<<16)|t
__device__ unsigned long long  g_cbg[(size_t)BB*TT];  // bg candidate keys
__device__ float               g_uw[BB];

// ---------------- K0: zero tiny scratch ----------------
__global__ void k0_zero() {
  int i = threadIdx.x;
  if (i < BB*NGT) g_gtmax[i] = 0u;
  if (i < BB) { g_cnt_fg[i] = 0; g_cnt_bg[i] = 0; }
}

// ---------------- K1: per-(b,g) max of positive IoUs ----------------
__global__ void k1_gtmax(const float* __restrict__ gt, const float* __restrict__ iminfo) {
  __shared__ float    s_gt[NGT*5];
  __shared__ unsigned s_max[NGT];
  int b = blockIdx.z, a = blockIdx.y, tid = threadIdx.x;
  int hw = blockIdx.x * 256 + tid;
  if (tid < NGT*5) s_gt[tid] = gt[b*NGT*5 + tid];
  if (tid < NGT)   s_max[tid] = 0u;
  __syncthreads();
  float img_h = iminfo[0], img_w = iminfo[1];
  int h = hw / FW, w = hw - h * FW;
  float sx = (float)(w * 16), sy = (float)(h * 16);
  float ax1 = c_anchors[a*4+0] + sx;
  float ay1 = c_anchors[a*4+1] + sy;
  float ax2 = c_anchors[a*4+2] + sx;
  float ay2 = c_anchors[a*4+3] + sy;
  bool inside = (ax1 >= 0.f) && (ay1 >= 0.f) && (ax2 < img_w) && (ay2 < img_h);
  float aw = __fadd_rn(__fsub_rn(ax2, ax1), 1.0f);
  float ah = __fadd_rn(__fsub_rn(ay2, ay1), 1.0f);
  float area = __fmul_rn(aw, ah);

  if (__ballot_sync(FULLM, inside)) {
    for (int g = 0; g < NGT; g++) {
      float gx1 = s_gt[g*5+0], gy1 = s_gt[g*5+1], gx2 = s_gt[g*5+2], gy2 = s_gt[g*5+3];
      float gw = __fadd_rn(__fsub_rn(gx2, gx1), 1.0f);
      float gh = __fadd_rn(__fsub_rn(gy2, gy1), 1.0f);
      bool gz = (gw == 1.0f) && (gh == 1.0f);
      float iw = __fadd_rn(__fsub_rn(fminf(ax2, gx2), fmaxf(ax1, gx1)), 1.0f);
      float ih = __fadd_rn(__fsub_rn(fminf(ay2, gy2), fmaxf(ay1, gy1)), 1.0f);
      float inter = __fmul_rn(fmaxf(iw, 0.0f), fmaxf(ih, 0.0f));
      bool need = inside && !gz && (inter > 0.0f);
      if (__ballot_sync(FULLM, need)) {
        unsigned fu = 0u;
        if (need) {
          float ga = __fmul_rn(gw, gh);
          float ua = __fsub_rn(__fadd_rn(area, ga), inter);
          float v  = __fdiv_rn(inter, ua);           // > 0
          fu = __float_as_uint(v) | 0x80000000u;     // order-preserving for positives
        }
        unsigned r = __reduce_max_sync(FULLM, fu);
        if ((tid & 31) == 0) atomicMax(&s_max[g], r);
      }
    }
  }
  __syncthreads();
  if (tid < NGT && s_max[tid]) atomicMax(&g_gtmax[b*NGT + tid], s_max[tid]);
}

// ---------------- K2: labels, targets -> out, RNG + compaction ----------------
__global__ void k2_main(const float* __restrict__ gt, const float* __restrict__ iminfo,
                        uint32_t kf0, uint32_t kf1, uint32_t kb0, uint32_t kb1,
                        float* __restrict__ out) {
  __shared__ float s_gt[NGT*5];
  __shared__ float s_gm[NGT];
  int b = blockIdx.z, a = blockIdx.y, tid = threadIdx.x;
  int hw = blockIdx.x * 256 + tid;
  if (tid < NGT*5) s_gt[tid] = gt[b*NGT*5 + tid];
  if (tid < NGT) {
    unsigned u_ = g_gtmax[b*NGT + tid];
    s_gm[tid] = u_ ? __uint_as_float(u_ ^ 0x80000000u) : -999.0f;
  }
  __syncthreads();
  float img_h = iminfo[0], img_w = iminfo[1];
  int h = hw / FW, w = hw - h * FW;
  float sx = (float)(w * 16), sy = (float)(h * 16);
  float ax1 = c_anchors[a*4+0] + sx;
  float ay1 = c_anchors[a*4+1] + sy;
  float ax2 = c_anchors[a*4+2] + sx;
  float ay2 = c_anchors[a*4+3] + sy;
  bool inside = (ax1 >= 0.f) && (ay1 >= 0.f) && (ax2 < img_w) && (ay2 < img_h);
  float aw = __fadd_rn(__fsub_rn(ax2, ax1), 1.0f);
  float ah = __fadd_rn(__fsub_rn(ay2, ay1), 1.0f);
  float area = __fmul_rn(aw, ah);

  float mx = -3.0f; int amax = 0; bool keep = false;
  if (__ballot_sync(FULLM, inside)) {
    for (int g = 0; g < NGT; g++) {
      float gx1 = s_gt[g*5+0], gy1 = s_gt[g*5+1], gx2 = s_gt[g*5+2], gy2 = s_gt[g*5+3];
      float gw = __fadd_rn(__fsub_rn(gx2, gx1), 1.0f);
      float gh = __fadd_rn(__fsub_rn(gy2, gy1), 1.0f);
      bool gz = (gw == 1.0f) && (gh == 1.0f);
      float iw = __fadd_rn(__fsub_rn(fminf(ax2, gx2), fmaxf(ax1, gx1)), 1.0f);
      float ih = __fadd_rn(__fsub_rn(fminf(ay2, gy2), fmaxf(ay1, gy1)), 1.0f);
      float inter = __fmul_rn(fmaxf(iw, 0.0f), fmaxf(ih, 0.0f));
      bool need = inside && !gz && (inter > 0.0f);
      float v = 0.0f;
      if (__ballot_sync(FULLM, need)) {
        if (need) {
          float ga = __fmul_rn(gw, gh);
          float ua = __fsub_rn(__fadd_rn(area, ga), inter);
          v = __fdiv_rn(inter, ua);
        }
      }
      keep = keep || (v == s_gm[g]);
      if (v > mx) { mx = v; amax = g; }   // first-occurrence argmax
    }
  }

  unsigned char L = 2;
  if (inside) L = (keep || mx >= 0.7f) ? 1 : ((mx < 0.3f) ? 0 : 2);
  size_t sidx = (size_t)b * TT + a * HW + hw;
  g_lab[sidx] = L;

  // bbox targets straight into output (coalesced planes)
  float4 tg = make_float4(0.f, 0.f, 0.f, 0.f);
  if (inside) {
    const float* g5 = &s_gt[amax*5];
    float ew = ax2 - ax1 + 1.0f, eh = ay2 - ay1 + 1.0f;
    float ecx = ax1 + 0.5f*ew,   ecy = ay1 + 0.5f*eh;
    float gw = g5[2] - g5[0] + 1.0f, gh = g5[3] - g5[1] + 1.0f;
    float gcx = g5[0] + 0.5f*gw,     gcy = g5[1] + 0.5f*gh;
    tg.x = (gcx - ecx) / ew;
    tg.y = (gcy - ecy) / eh;
    tg.z = logf(gw / ew);
    tg.w = logf(gh / eh);
  }
  float* tgt_o = out + (size_t)BB * AA * HW;
  size_t cb = ((size_t)b * 36 + a * 4) * HW + hw;
  tgt_o[cb        ] = tg.x;
  tgt_o[cb +   HW ] = tg.y;
  tgt_o[cb + 2*HW ] = tg.z;
  tgt_o[cb + 3*HW ] = tg.w;

  // RNG draw + warp-aggregated compaction of candidate keys
  unsigned ballot_fg = __ballot_sync(FULLM, L == 1);
  unsigned ballot_bg = __ballot_sync(FULLM, L == 0);
  unsigned long long key = 0ull;
  int t = hw * 9 + a;                      // original anchor index (t-order)
  if (L <= 1) {
    uint32_t key0 = L ? kf0 : kb0, key1 = L ? kf1 : kb1;
    uint32_t o0, o1;
    uint32_t cnt = (uint32_t)(b * TT + t);
    tf2x32(key0, key1, 0u, cnt, o0, o1);
    unsigned m = (o0 ^ o1) >> 9;           // 23-bit, monotone in uniform
    key = ((unsigned long long)m << 16) | (unsigned)t;   // unique 39-bit key
  }
  int lane = tid & 31;
  if (L == 1) {
    unsigned mask = ballot_fg;
    int leader = __ffs(mask) - 1;
    int base = 0;
    if (lane == leader) base = atomicAdd(&g_cnt_fg[b], __popc(mask));
    base = __shfl_sync(mask, base, leader);
    int off = __popc(mask & ((1u << lane) - 1u));
    g_cfg[(size_t)b * TT + base + off] = key;
  } else if (L == 0) {
    unsigned mask = ballot_bg;
    int leader = __ffs(mask) - 1;
    int base = 0;
    if (lane == leader) base = atomicAdd(&g_cnt_bg[b], __popc(mask));
    base = __shfl_sync(mask, base, leader);
    int off = __popc(mask & ((1u << lane) - 1u));
    g_cbg[(size_t)b * TT + base + off] = key;
  }
}

// ---------------- K3: exact radix select on 39-bit keys ----------------
__device__ __forceinline__ int blockInclScan(int local, int* s_wsum) {
  int lane = threadIdx.x & 31, wid = threadIdx.x >> 5;
  int v = local;
#pragma unroll
  for (int o = 1; o < 32; o <<= 1) { int n = __shfl_up_sync(FULLM, v, o); if (lane >= o) v += n; }
  if (lane == 31) s_wsum[wid] = v;
  __syncthreads();
  if (wid == 0) {
    int wv = s_wsum[lane];
#pragma unroll
    for (int o = 1; o < 32; o <<= 1) { int n = __shfl_up_sync(FULLM, wv, o); if (lane >= o) wv += n; }
    s_wsum[lane] = wv;
  }
  __syncthreads();
  return v + (wid ? s_wsum[wid-1] : 0);
}

__global__ void __launch_bounds__(1024) k3_select() {
  __shared__ unsigned s_hist[8192];
  __shared__ int s_wsum[32];
  __shared__ int s_sel[2];   // {bin, cumBefore}
  int b = blockIdx.x, cls = blockIdx.y, tid = threadIdx.x;

  int nfg = g_cnt_fg[b];
  int n   = cls ? nfg : g_cnt_bg[b];
  int kept_fg = min(nfg, FG_K);
  int k = cls ? FG_K : (RPN_BATCH_K - kept_fg);
  if (cls == 0 && tid == 0)
    g_uw[b] = 1.0f / (float)(kept_fg + min(n, k));
  if (n <= k) return;

  const unsigned long long* keys = (cls ? g_cfg : g_cbg) + (size_t)b * TT;
  unsigned char* lab = g_lab + (size_t)b * TT;

  unsigned long long prefix = 0ull;
  int kk = k;
#pragma unroll
  for (int lvl = 0; lvl < 3; lvl++) {
    int shift = 26 - 13 * lvl;
    for (int i = tid; i < 8192; i += 1024) s_hist[i] = 0u;
    __syncthreads();
    for (int i = tid; i < n; i += 1024) {
      unsigned long long key = keys[i];
      if (lvl == 0 || (key >> (shift + 13)) == prefix)
        atomicAdd(&s_hist[(unsigned)(key >> shift) & 8191u], 1u);
    }
    __syncthreads();
    int base = tid * 8;
    int local = 0;
#pragma unroll
    for (int j = 0; j < 8; j++) local += (int)s_hist[base + j];
    int incl = blockInclScan(local, s_wsum);
    int excl = incl - local;
    if (kk > excl && kk <= incl) {
      int c = excl;
      for (int j = 0; j < 8; j++) {
        int hh = (int)s_hist[base + j];
        if (c + hh >= kk) { s_sel[0] = base + j; s_sel[1] = c; break; }
        c += hh;
      }
    }
    __syncthreads();
    prefix = (prefix << 13) | (unsigned)s_sel[0];
    kk -= s_sel[1];
    __syncthreads();
  }
  unsigned long long kstar = prefix;   // exact k-th smallest key (keys unique)

  // demote everything above the threshold
  for (int i = tid; i < n; i += 1024) {
    unsigned long long key = keys[i];
    if (key > kstar) {
      int t = (int)(key & 0xFFFFull);
      lab[(t % 9) * HW + t / 9] = 2;
    }
  }
}

// ---------------- K4: labels + in/out weights (vectorized) ----------------
__global__ void k4_out(float* __restrict__ out) {
  int idx = blockIdx.x * 320 + threadIdx.x;   // 0..1599
  int b = blockIdx.y;
  int hw = idx * 4;
  float u = g_uw[b];
  const size_t OFF1 = (size_t)BB * AA * HW;
  const size_t PL   = (size_t)BB * 36 * HW;
  float* lab_o  = out;
  float* inw_o  = out + OFF1 + PL;
  float* outw_o = out + OFF1 + 2 * PL;
#pragma unroll
  for (int a = 0; a < AA; a++) {
    uchar4 L4 = *reinterpret_cast<const uchar4*>(&g_lab[(size_t)b * TT + a * HW + hw]);
    float4 lv, iw, ow;
    lv.x = (L4.x == 2) ? -1.f : (float)L4.x;
    lv.y = (L4.y == 2) ? -1.f : (float)L4.y;
    lv.z = (L4.z == 2) ? -1.f : (float)L4.z;
    lv.w = (L4.w == 2) ? -1.f : (float)L4.w;
    iw.x = (L4.x == 1) ? 1.f : 0.f;
    iw.y = (L4.y == 1) ? 1.f : 0.f;
    iw.z = (L4.z == 1) ? 1.f : 0.f;
    iw.w = (L4.w == 1) ? 1.f : 0.f;
    ow.x = (L4.x != 2) ? u : 0.f;
    ow.y = (L4.y != 2) ? u : 0.f;
    ow.z = (L4.z != 2) ? u : 0.f;
    ow.w = (L4.w != 2) ? u : 0.f;
    *reinterpret_cast<float4*>(&lab_o[((size_t)b * AA + a) * HW + hw]) = lv;
    size_t cbase = ((size_t)b * 36 + a * 4) * HW + hw;
#pragma unroll
    for (int c = 0; c < 4; c++) {
      *reinterpret_cast<float4*>(&inw_o [cbase + (size_t)c * HW]) = iw;
      *reinterpret_cast<float4*>(&outw_o[cbase + (size_t)c * HW]) = ow;
    }
  }
}

// ---------------- host ----------------
extern "C" void kernel_launch(void* const* d_in, const int* in_sizes, int n_in,
                              void* d_out, int out_size) {
  const float* gt     = (const float*)d_in[1];   // gt_boxes [32,20,5]
  const float* iminfo = (const float*)d_in[2];   // im_info [32,3]
  float* out = (float*)d_out;

  uint32_t kf0, kf1, kb0, kb1;
  tf2x32(0u, 42u, 0u, 0u, kf0, kf1);
  tf2x32(0u, 42u, 0u, 1u, kb0, kb1);

  k0_zero  <<<1, 1024>>>();
  k1_gtmax <<<dim3(HW/256, AA, BB), 256>>>(gt, iminfo);
  k2_main  <<<dim3(HW/256, AA, BB), 256>>>(gt, iminfo, kf0, kf1, kb0, kb1, out);
  k3_select<<<dim3(BB, 2), 1024>>>();
  k4_out   <<<dim3(5, BB), 320>>>(out);
}

// round 5
// speedup vs baseline: 2.3847x; 1.0094x over previous
#include <cuda_runtime.h>
#include <stdint.h>

#define BB 32
#define NGT 20
#define FH 64
#define FW 100
#define AA 9
#define HW (FH*FW)      // 6400
#define TT (HW*AA)      // 57600
#define FG_K 128
#define RPN_BATCH_K 256
#define FULLM 0xffffffffu

__device__ __constant__ float c_anchors[AA*4] = {
  -84.f,  -40.f,  99.f,  55.f,
 -176.f,  -88.f, 191.f, 103.f,
 -360.f, -184.f, 375.f, 199.f,
  -56.f,  -56.f,  71.f,  71.f,
 -120.f, -120.f, 135.f, 135.f,
 -248.f, -248.f, 263.f, 263.f,
  -36.f,  -80.f,  51.f,  95.f,
  -80.f, -168.f,  95.f, 183.f,
 -168.f, -344.f, 183.f, 359.f
};

// ---------------- Threefry-2x32 (20 rounds), matches JAX partitionable ----------------
__host__ __device__ __forceinline__ void tf2x32(uint32_t k0, uint32_t k1,
                                                uint32_t x0, uint32_t x1,
                                                uint32_t& o0, uint32_t& o1) {
  uint32_t ks2 = k0 ^ k1 ^ 0x1BD11BDAu;
  x0 += k0; x1 += k1;
#define TF_RND(r) { x0 += x1; x1 = (x1 << (r)) | (x1 >> (32 - (r))); x1 ^= x0; }
  TF_RND(13) TF_RND(15) TF_RND(26) TF_RND(6)   x0 += k1;  x1 += ks2 + 1u;
  TF_RND(17) TF_RND(29) TF_RND(16) TF_RND(24)  x0 += ks2; x1 += k0  + 2u;
  TF_RND(13) TF_RND(15) TF_RND(26) TF_RND(6)   x0 += k0;  x1 += k1  + 3u;
  TF_RND(17) TF_RND(29) TF_RND(16) TF_RND(24)  x0 += k1;  x1 += ks2 + 4u;
  TF_RND(13) TF_RND(15) TF_RND(26) TF_RND(6)   x0 += ks2; x1 += k0  + 5u;
#undef TF_RND
  o0 = x0; o1 = x1;
}

// ---------------- scratch (device globals; no allocations) ----------------
__device__ unsigned int        g_gtmax[BB*NGT];  // biased-float max of positive IoUs (0 = none)
__device__ int                 g_cnt_fg[BB];
__device__ int                 g_cnt_bg[BB];
__device__ unsigned char       g_lab[BB*TT];     // s = a*HW+hw order; 0=bg,1=fg,2=dontcare
__device__ unsigned long long  g_cfg[(size_t)BB*TT];  // fg candidate keys (m<<16)|t
__device__ unsigned long long  g_cbg[(size_t)BB*TT];  // bg candidate keys
__device__ float               g_uw[BB];

// ---------------- K0: zero tiny scratch ----------------
__global__ void k0_zero() {
  int i = threadIdx.x;
  if (i < BB*NGT) g_gtmax[i] = 0u;
  if (i < BB) { g_cnt_fg[i] = 0; g_cnt_bg[i] = 0; }
}

// ---------------- K1: per-(b,g) max of positive IoUs ----------------
__global__ void k1_gtmax(const float* __restrict__ gt, const float* __restrict__ iminfo) {
  __shared__ float    s_gt[NGT*5];
  __shared__ unsigned s_max[NGT];
  int b = blockIdx.z, a = blockIdx.y, tid = threadIdx.x;
  int hw = blockIdx.x * 256 + tid;
  if (tid < NGT*5) s_gt[tid] = gt[b*NGT*5 + tid];
  if (tid < NGT)   s_max[tid] = 0u;
  __syncthreads();
  float img_h = iminfo[0], img_w = iminfo[1];
  int h = hw / FW, w = hw - h * FW;
  float sx = (float)(w * 16), sy = (float)(h * 16);
  float ax1 = c_anchors[a*4+0] + sx;
  float ay1 = c_anchors[a*4+1] + sy;
  float ax2 = c_anchors[a*4+2] + sx;
  float ay2 = c_anchors[a*4+3] + sy;
  bool inside = (ax1 >= 0.f) && (ay1 >= 0.f) && (ax2 < img_w) && (ay2 < img_h);
  float aw = __fadd_rn(__fsub_rn(ax2, ax1), 1.0f);
  float ah = __fadd_rn(__fsub_rn(ay2, ay1), 1.0f);
  float area = __fmul_rn(aw, ah);

  if (__ballot_sync(FULLM, inside)) {
    for (int g = 0; g < NGT; g++) {
      float gx1 = s_gt[g*5+0], gy1 = s_gt[g*5+1], gx2 = s_gt[g*5+2], gy2 = s_gt[g*5+3];
      float gw = __fadd_rn(__fsub_rn(gx2, gx1), 1.0f);
      float gh = __fadd_rn(__fsub_rn(gy2, gy1), 1.0f);
      bool gz = (gw == 1.0f) && (gh == 1.0f);
      float iw = __fadd_rn(__fsub_rn(fminf(ax2, gx2), fmaxf(ax1, gx1)), 1.0f);
      float ih = __fadd_rn(__fsub_rn(fminf(ay2, gy2), fmaxf(ay1, gy1)), 1.0f);
      float inter = __fmul_rn(fmaxf(iw, 0.0f), fmaxf(ih, 0.0f));
      bool need = inside && !gz && (inter > 0.0f);
      if (__ballot_sync(FULLM, need)) {
        unsigned fu = 0u;
        if (need) {
          float ga = __fmul_rn(gw, gh);
          float ua = __fsub_rn(__fadd_rn(area, ga), inter);
          float v  = __fdiv_rn(inter, ua);           // > 0
          fu = __float_as_uint(v) | 0x80000000u;     // order-preserving for positives
        }
        unsigned r = __reduce_max_sync(FULLM, fu);
        if ((tid & 31) == 0) atomicMax(&s_max[g], r);
      }
    }
  }
  __syncthreads();
  if (tid < NGT && s_max[tid]) atomicMax(&g_gtmax[b*NGT + tid], s_max[tid]);
}

// ---------------- K2: labels, targets -> out, RNG + compaction ----------------
__global__ void k2_main(const float* __restrict__ gt, const float* __restrict__ iminfo,
                        uint32_t kf0, uint32_t kf1, uint32_t kb0, uint32_t kb1,
                        float* __restrict__ out) {
  __shared__ float s_gt[NGT*5];
  __shared__ float s_gm[NGT];
  int b = blockIdx.z, a = blockIdx.y, tid = threadIdx.x;
  int hw = blockIdx.x * 256 + tid;
  if (tid < NGT*5) s_gt[tid] = gt[b*NGT*5 + tid];
  if (tid < NGT) {
    unsigned u_ = g_gtmax[b*NGT + tid];
    s_gm[tid] = u_ ? __uint_as_float(u_ ^ 0x80000000u) : -999.0f;
  }
  __syncthreads();
  float img_h = iminfo[0], img_w = iminfo[1];
  int h = hw / FW, w = hw - h * FW;
  float sx = (float)(w * 16), sy = (float)(h * 16);
  float ax1 = c_anchors[a*4+0] + sx;
  float ay1 = c_anchors[a*4+1] + sy;
  float ax2 = c_anchors[a*4+2] + sx;
  float ay2 = c_anchors[a*4+3] + sy;
  bool inside = (ax1 >= 0.f) && (ay1 >= 0.f) && (ax2 < img_w) && (ay2 < img_h);
  float aw = __fadd_rn(__fsub_rn(ax2, ax1), 1.0f);
  float ah = __fadd_rn(__fsub_rn(ay2, ay1), 1.0f);
  float area = __fmul_rn(aw, ah);

  float mx = -3.0f; int amax = 0; bool keep = false;
  if (__ballot_sync(FULLM, inside)) {
    for (int g = 0; g < NGT; g++) {
      float gx1 = s_gt[g*5+0], gy1 = s_gt[g*5+1], gx2 = s_gt[g*5+2], gy2 = s_gt[g*5+3];
      float gw = __fadd_rn(__fsub_rn(gx2, gx1), 1.0f);
      float gh = __fadd_rn(__fsub_rn(gy2, gy1), 1.0f);
      bool gz = (gw == 1.0f) && (gh == 1.0f);
      float iw = __fadd_rn(__fsub_rn(fminf(ax2, gx2), fmaxf(ax1, gx1)), 1.0f);
      float ih = __fadd_rn(__fsub_rn(fminf(ay2, gy2), fmaxf(ay1, gy1)), 1.0f);
      float inter = __fmul_rn(fmaxf(iw, 0.0f), fmaxf(ih, 0.0f));
      bool need = inside && !gz && (inter > 0.0f);
      float v = 0.0f;
      if (__ballot_sync(FULLM, need)) {
        if (need) {
          float ga = __fmul_rn(gw, gh);
          float ua = __fsub_rn(__fadd_rn(area, ga), inter);
          v = __fdiv_rn(inter, ua);
        }
      }
      keep = keep || (v == s_gm[g]);
      if (v > mx) { mx = v; amax = g; }   // first-occurrence argmax
    }
  }

  unsigned char L = 2;
  if (inside) L = (keep || mx >= 0.7f) ? 1 : ((mx < 0.3f) ? 0 : 2);
  size_t sidx = (size_t)b * TT + a * HW + hw;
  g_lab[sidx] = L;

  // bbox targets straight into output (coalesced planes)
  float4 tg = make_float4(0.f, 0.f, 0.f, 0.f);
  if (inside) {
    const float* g5 = &s_gt[amax*5];
    float ew = ax2 - ax1 + 1.0f, eh = ay2 - ay1 + 1.0f;
    float ecx = ax1 + 0.5f*ew,   ecy = ay1 + 0.5f*eh;
    float gw = g5[2] - g5[0] + 1.0f, gh = g5[3] - g5[1] + 1.0f;
    float gcx = g5[0] + 0.5f*gw,     gcy = g5[1] + 0.5f*gh;
    tg.x = (gcx - ecx) / ew;
    tg.y = (gcy - ecy) / eh;
    tg.z = logf(gw / ew);
    tg.w = logf(gh / eh);
  }
  float* tgt_o = out + (size_t)BB * AA * HW;
  size_t cb = ((size_t)b * 36 + a * 4) * HW + hw;
  tgt_o[cb        ] = tg.x;
  tgt_o[cb +   HW ] = tg.y;
  tgt_o[cb + 2*HW ] = tg.z;
  tgt_o[cb + 3*HW ] = tg.w;

  // RNG draw + warp-aggregated compaction of candidate keys
  unsigned ballot_fg = __ballot_sync(FULLM, L == 1);
  unsigned ballot_bg = __ballot_sync(FULLM, L == 0);
  unsigned long long key = 0ull;
  int t = hw * 9 + a;                      // original anchor index (t-order)
  if (L <= 1) {
    uint32_t key0 = L ? kf0 : kb0, key1 = L ? kf1 : kb1;
    uint32_t o0, o1;
    uint32_t cnt = (uint32_t)(b * TT + t);
    tf2x32(key0, key1, 0u, cnt, o0, o1);
    unsigned m = (o0 ^ o1) >> 9;           // 23-bit, monotone in uniform
    key = ((unsigned long long)m << 16) | (unsigned)t;   // unique 39-bit key
  }
  int lane = tid & 31;
  if (L == 1) {
    unsigned mask = ballot_fg;
    int leader = __ffs(mask) - 1;
    int base = 0;
    if (lane == leader) base = atomicAdd(&g_cnt_fg[b], __popc(mask));
    base = __shfl_sync(mask, base, leader);
    int off = __popc(mask & ((1u << lane) - 1u));
    g_cfg[(size_t)b * TT + base + off] = key;
  } else if (L == 0) {
    unsigned mask = ballot_bg;
    int leader = __ffs(mask) - 1;
    int base = 0;
    if (lane == leader) base = atomicAdd(&g_cnt_bg[b], __popc(mask));
    base = __shfl_sync(mask, base, leader);
    int off = __popc(mask & ((1u << lane) - 1u));
    g_cbg[(size_t)b * TT + base + off] = key;
  }
}

// ---------------- K3: exact radix select on 39-bit keys ----------------
__device__ __forceinline__ int blockInclScan(int local, int* s_wsum) {
  int lane = threadIdx.x & 31, wid = threadIdx.x >> 5;
  int v = local;
#pragma unroll
  for (int o = 1; o < 32; o <<= 1) { int n = __shfl_up_sync(FULLM, v, o); if (lane >= o) v += n; }
  if (lane == 31) s_wsum[wid] = v;
  __syncthreads();
  if (wid == 0) {
    int wv = s_wsum[lane];
#pragma unroll
    for (int o = 1; o < 32; o <<= 1) { int n = __shfl_up_sync(FULLM, wv, o); if (lane >= o) wv += n; }
    s_wsum[lane] = wv;
  }
  __syncthreads();
  return v + (wid ? s_wsum[wid-1] : 0);
}

__global__ void __launch_bounds__(1024) k3_select() {
  __shared__ unsigned s_hist[8192];
  __shared__ int s_wsum[32];
  __shared__ int s_sel[2];   // {bin, cumBefore}
  int b = blockIdx.x, cls = blockIdx.y, tid = threadIdx.x;

  int nfg = g_cnt_fg[b];
  int n   = cls ? nfg : g_cnt_bg[b];
  int kept_fg = min(nfg, FG_K);
  int k = cls ? FG_K : (RPN_BATCH_K - kept_fg);
  if (cls == 0 && tid == 0)
    g_uw[b] = 1.0f / (float)(kept_fg + min(n, k));
  if (n <= k) return;

  const unsigned long long* keys = (cls ? g_cfg : g_cbg) + (size_t)b * TT;
  unsigned char* lab = g_lab + (size_t)b * TT;

  unsigned long long prefix = 0ull;
  int kk = k;
#pragma unroll
  for (int lvl = 0; lvl < 3; lvl++) {
    int shift = 26 - 13 * lvl;
    for (int i = tid; i < 8192; i += 1024) s_hist[i] = 0u;
    __syncthreads();
    for (int i = tid; i < n; i += 1024) {
      unsigned long long key = keys[i];
      if (lvl == 0 || (key >> (shift + 13)) == prefix)
        atomicAdd(&s_hist[(unsigned)(key >> shift) & 8191u], 1u);
    }
    __syncthreads();
    int base = tid * 8;
    int local = 0;
#pragma unroll
    for (int j = 0; j < 8; j++) local += (int)s_hist[base + j];
    int incl = blockInclScan(local, s_wsum);
    int excl = incl - local;
    if (kk > excl && kk <= incl) {
      int c = excl;
      for (int j = 0; j < 8; j++) {
        int hh = (int)s_hist[base + j];
        if (c + hh >= kk) { s_sel[0] = base + j; s_sel[1] = c; break; }
        c += hh;
      }
    }
    __syncthreads();
    prefix = (prefix << 13) | (unsigned)s_sel[0];
    kk -= s_sel[1];
    __syncthreads();
  }
  unsigned long long kstar = prefix;   // exact k-th smallest key (keys unique)

  // demote everything above the threshold
  for (int i = tid; i < n; i += 1024) {
    unsigned long long key = keys[i];
    if (key > kstar) {
      int t = (int)(key & 0xFFFFull);
      lab[(t % 9) * HW + t / 9] = 2;
    }
  }
}

// ---------------- K4: labels + in/out weights (vectorized) ----------------
__global__ void k4_out(float* __restrict__ out) {
  int idx = blockIdx.x * 320 + threadIdx.x;   // 0..1599
  int b = blockIdx.y;
  int hw = idx * 4;
  float u = g_uw[b];
  const size_t OFF1 = (size_t)BB * AA * HW;
  const size_t PL   = (size_t)BB * 36 * HW;
  float* lab_o  = out;
  float* inw_o  = out + OFF1 + PL;
  float* outw_o = out + OFF1 + 2 * PL;
#pragma unroll
  for (int a = 0; a < AA; a++) {
    uchar4 L4 = *reinterpret_cast<const uchar4*>(&g_lab[(size_t)b * TT + a * HW + hw]);
    float4 lv, iw, ow;
    lv.x = (L4.x == 2) ? -1.f : (float)L4.x;
    lv.y = (L4.y == 2) ? -1.f : (float)L4.y;
    lv.z = (L4.z == 2) ? -1.f : (float)L4.z;
    lv.w = (L4.w == 2) ? -1.f : (float)L4.w;
    iw.x = (L4.x == 1) ? 1.f : 0.f;
    iw.y = (L4.y == 1) ? 1.f : 0.f;
    iw.z = (L4.z == 1) ? 1.f : 0.f;
    iw.w = (L4.w == 1) ? 1.f : 0.f;
    ow.x = (L4.x != 2) ? u : 0.f;
    ow.y = (L4.y != 2) ? u : 0.f;
    ow.z = (L4.z != 2) ? u : 0.f;
    ow.w = (L4.w != 2) ? u : 0.f;
    *reinterpret_cast<float4*>(&lab_o[((size_t)b * AA + a) * HW + hw]) = lv;
    size_t cbase = ((size_t)b * 36 + a * 4) * HW + hw;
#pragma unroll
    for (int c = 0; c < 4; c++) {
      *reinterpret_cast<float4*>(&inw_o [cbase + (size_t)c * HW]) = iw;
      *reinterpret_cast<float4*>(&outw_o[cbase + (size_t)c * HW]) = ow;
    }
  }
}

// ---------------- host ----------------
extern "C" void kernel_launch(void* const* d_in, const int* in_sizes, int n_in,
                              void* d_out, int out_size) {
  const float* gt     = (const float*)d_in[1];   // gt_boxes [32,20,5]
  const float* iminfo = (const float*)d_in[2];   // im_info [32,3]
  float* out = (float*)d_out;

  uint32_t kf0, kf1, kb0, kb1;
  tf2x32(0u, 42u, 0u, 0u, kf0, kf1);
  tf2x32(0u, 42u, 0u, 1u, kb0, kb1);

  k0_zero  <<<1, 1024>>>();
  k1_gtmax <<<dim3(HW/256, AA, BB), 256>>>(gt, iminfo);
  k2_main  <<<dim3(HW/256, AA, BB), 256>>>(gt, iminfo, kf0, kf1, kb0, kb1, out);
  k3_select<<<dim3(BB, 2), 1024>>>();
  k4_out   <<<dim3(5, BB), 320>>>(out);
}